// round 1
// baseline (speedup 1.0000x reference)
#include <cuda_runtime.h>
#include <math_constants.h>

// Problem constants
#define CC   128          // input channels
#define DD   64           // embedding dim
#define KK   512          // codebook size
#define PP   4096         // H*W
#define NB   32           // batch
#define NPIX (NB*PP)      // 131072 pixels
#define NOUT (NPIX*DD)    // 8388608 output elems (quantized_st)

#define NTHREADS 256
#define BPX      256      // pixels per CTA (== NTHREADS, 1 px/thread)
#define XCH      32       // x channels staged per chunk

// smem layout (floats): ct[512][64] | ws[64][128] | xs[32][256] | cc[512]
#define SM_CT 0
#define SM_WS (KK*DD)                 // 32768
#define SM_XS (SM_WS + DD*CC)         // 40960
#define SM_CC (SM_XS + XCH*BPX)       // 49152
#define SM_TOTAL_FLOATS (SM_CC + KK)  // 49664 floats = 198656 B

__device__ double g_loss_sum;

__global__ void vq_init_kernel() { g_loss_sum = 0.0; }

__global__ void __launch_bounds__(NTHREADS, 1)
vq_main_kernel(const float* __restrict__ x,
               const float* __restrict__ w,
               const float* __restrict__ bias,
               const float* __restrict__ cb,
               float* __restrict__ out)
{
    extern __shared__ float smem[];
    float* ct = smem + SM_CT;   // codebook [K][D], row-major (natural)
    float* ws = smem + SM_WS;   // conv weight [D][C]
    float* xs = smem + SM_XS;   // x chunk [XCH][BPX]
    float* cc = smem + SM_CC;   // ||c_k||^2

    const int t     = threadIdx.x;
    const int bpix  = blockIdx.x * BPX;     // global pixel base
    const int bb    = bpix / PP;            // batch index
    const int pbase = bpix % PP;            // pixel base within batch
    const int p     = pbase + t;            // this thread's pixel in batch

    // ---- Stage codebook + weights (coalesced, conflict-free) ----
    #pragma unroll 4
    for (int e = t; e < KK*DD; e += NTHREADS) ct[e] = cb[e];
    #pragma unroll 4
    for (int e = t; e < DD*CC; e += NTHREADS) ws[e] = w[e];
    __syncthreads();

    // ---- cc[k] = sum_i c_ki^2 ----
    for (int k = t; k < KK; k += NTHREADS) {
        float s = 0.f;
        #pragma unroll 8
        for (int i = 0; i < DD; i++) { float v = ct[k*DD + i]; s = fmaf(v, v, s); }
        cc[k] = s;
    }

    // ---- Conv: z[d] = sum_c w[d][c] * x[c][p] + b[d] ----
    float z[DD];
    #pragma unroll
    for (int d = 0; d < DD; d++) z[d] = 0.f;

    for (int ch = 0; ch < CC; ch += XCH) {
        __syncthreads();
        #pragma unroll 8
        for (int r = 0; r < XCH; r++)
            xs[r*BPX + t] = x[(bb*CC + ch + r)*PP + pbase + t];
        __syncthreads();

        #pragma unroll
        for (int c = 0; c < XCH; c += 4) {
            const float x0 = xs[(c+0)*BPX + t];
            const float x1 = xs[(c+1)*BPX + t];
            const float x2 = xs[(c+2)*BPX + t];
            const float x3 = xs[(c+3)*BPX + t];
            #pragma unroll
            for (int d = 0; d < DD; d++) {
                const float4 wv = *(const float4*)&ws[d*CC + ch + c];
                z[d] = fmaf(wv.x, x0, z[d]);
                z[d] = fmaf(wv.y, x1, z[d]);
                z[d] = fmaf(wv.z, x2, z[d]);
                z[d] = fmaf(wv.w, x3, z[d]);
            }
        }
    }
    #pragma unroll
    for (int d = 0; d < DD; d++) z[d] += __ldg(&bias[d]);

    // ---- s = ||z||^2 ----
    float s = 0.f;
    #pragma unroll
    for (int d = 0; d < DD; d++) s = fmaf(z[d], z[d], s);

    // ---- argmin_k  (s - 2 z.c_k) + ||c_k||^2  (first-occurrence tie-break) ----
    float bestd = CUDART_INF_F;
    int   bestk = 0;
    for (int k0 = 0; k0 < KK; k0 += 16) {
        float acc[16];
        #pragma unroll
        for (int j = 0; j < 16; j++) acc[j] = 0.f;
        #pragma unroll
        for (int i = 0; i < DD; i += 4) {
            const float z0 = z[i+0], z1 = z[i+1], z2 = z[i+2], z3 = z[i+3];
            #pragma unroll
            for (int j = 0; j < 16; j++) {
                const float4 cv = *(const float4*)&ct[(k0 + j)*DD + i];  // broadcast
                acc[j] = fmaf(cv.x, z0, acc[j]);
                acc[j] = fmaf(cv.y, z1, acc[j]);
                acc[j] = fmaf(cv.z, z2, acc[j]);
                acc[j] = fmaf(cv.w, z3, acc[j]);
            }
        }
        #pragma unroll
        for (int j = 0; j < 16; j++) {
            const float dd = (s - 2.f*acc[j]) + cc[k0 + j];
            if (dd < bestd) { bestd = dd; bestk = k0 + j; }
        }
    }

    // ---- Gather winning code (L2-resident), write out = z + (q - z), loss ----
    const float4* qv = (const float4*)(cb + bestk*DD);
    float lsum = 0.f;
    const int outbase = bb*DD*PP + pbase + t;
    #pragma unroll
    for (int i4 = 0; i4 < DD/4; i4++) {
        const float4 q = __ldg(&qv[i4]);
        {
            const float zz = z[i4*4+0]; const float df = q.x - zz;
            out[outbase + (i4*4+0)*PP] = zz + df; lsum = fmaf(df, df, lsum);
        }
        {
            const float zz = z[i4*4+1]; const float df = q.y - zz;
            out[outbase + (i4*4+1)*PP] = zz + df; lsum = fmaf(df, df, lsum);
        }
        {
            const float zz = z[i4*4+2]; const float df = q.z - zz;
            out[outbase + (i4*4+2)*PP] = zz + df; lsum = fmaf(df, df, lsum);
        }
        {
            const float zz = z[i4*4+3]; const float df = q.w - zz;
            out[outbase + (i4*4+3)*PP] = zz + df; lsum = fmaf(df, df, lsum);
        }
    }

    // ---- Loss reduction: warp shfl + one double atomic per warp ----
    double dl = (double)lsum;
    #pragma unroll
    for (int o = 16; o > 0; o >>= 1)
        dl += __shfl_down_sync(0xffffffffu, dl, o);
    if ((t & 31) == 0) atomicAdd(&g_loss_sum, dl);
}

__global__ void vq_fin_kernel(float* __restrict__ out, int out_size)
{
    if (out_size > NOUT) {
        const float m = (float)(g_loss_sum / (double)NOUT);
        out[NOUT] = 0.25f*m + m;   // commitment + embedding loss
    }
}

extern "C" void kernel_launch(void* const* d_in, const int* in_sizes, int n_in,
                              void* d_out, int out_size)
{
    const float* x    = (const float*)d_in[0];
    const float* w    = (const float*)d_in[1];
    const float* bias = (const float*)d_in[2];
    const float* cb   = (const float*)d_in[3];
    float* out = (float*)d_out;

    const size_t smem_bytes = SM_TOTAL_FLOATS * sizeof(float);  // 198656 B
    cudaFuncSetAttribute(vq_main_kernel,
                         cudaFuncAttributeMaxDynamicSharedMemorySize,
                         (int)smem_bytes);

    vq_init_kernel<<<1, 1>>>();
    vq_main_kernel<<<NPIX / BPX, NTHREADS, smem_bytes>>>(x, w, bias, cb, out);
    vq_fin_kernel<<<1, 1>>>(out, out_size);
}

// round 4
// speedup vs baseline: 1.0436x; 1.0436x over previous
#include <cuda_runtime.h>
#include <cstdint>
#include <math_constants.h>

#define CIN    128
#define DIM    64
#define KCODES 512
#define PPIX   4096
#define NPIX   131072
#define NOUTE  (NPIX*DIM)
#define TILE   128
#define NTILES (NPIX/TILE)
#define THREADS 128
#define ZSTRIDE 68     // padded float stride (conflict-free fragment loads)

// smem byte offsets
#define SM_WS    0          // 64*128 f32           = 32768
#define SM_CT    32768      // 512*68 tf32(u32)     = 139264
#define SM_Z     172032     // 128*68 f32           = 34816
#define SM_CCS   206848     // 512 f32              = 2048
#define SM_S     208896     // 128 f32              = 512
#define SM_KIDX  209408     // 128 i32              = 512
#define SM_CM    209920     // margin coeff         = 16
#define SM_TOTAL 209936

__device__ double g_loss_sum;
__global__ void vq_init_kernel() { g_loss_sum = 0.0; }

__device__ __forceinline__ uint32_t f2tf32(float f) {
    uint32_t u; asm("cvt.rna.tf32.f32 %0, %1;" : "=r"(u) : "f"(f)); return u;
}

__device__ __forceinline__ void mma8(float& c0, float& c1, float& c2, float& c3,
                                     uint32_t a0, uint32_t a1, uint32_t a2, uint32_t a3,
                                     uint32_t b0, uint32_t b1) {
    asm volatile("mma.sync.aligned.m16n8k8.row.col.f32.tf32.tf32.f32 "
                 "{%0,%1,%2,%3}, {%4,%5,%6,%7}, {%8,%9}, {%0,%1,%2,%3};"
                 : "+f"(c0), "+f"(c1), "+f"(c2), "+f"(c3)
                 : "r"(a0), "r"(a1), "r"(a2), "r"(a3), "r"(b0), "r"(b1));
}

// ---- exact conv, identical fmaf chain to the round-1 bitwise-verified kernel ----
__device__ __forceinline__ void conv_pixel(const float* __restrict__ x,
                                           const float* __restrict__ bias,
                                           const float* ws, int tile, int t, float* z) {
    const int P  = tile * TILE + t;
    const int bb = P >> 12;
    const int pp = P & 4095;
    const float* xp = x + (bb * CIN) * PPIX + pp;
#pragma unroll
    for (int d = 0; d < DIM; d++) z[d] = 0.f;
    for (int ch = 0; ch < CIN; ch += 16) {
        float xr[16];
#pragma unroll
        for (int j = 0; j < 16; j++) xr[j] = __ldg(&xp[(ch + j) * PPIX]);
#pragma unroll
        for (int c = 0; c < 16; c += 4) {
            const float x0 = xr[c], x1 = xr[c+1], x2 = xr[c+2], x3 = xr[c+3];
#pragma unroll
            for (int d = 0; d < DIM; d++) {
                const float4 wv = *(const float4*)&ws[d * CIN + ch + c];
                z[d] = fmaf(wv.x, x0, z[d]);
                z[d] = fmaf(wv.y, x1, z[d]);
                z[d] = fmaf(wv.z, x2, z[d]);
                z[d] = fmaf(wv.w, x3, z[d]);
            }
        }
    }
#pragma unroll
    for (int d = 0; d < DIM; d++) z[d] += __ldg(&bias[d]);
}

__global__ void __launch_bounds__(THREADS, 1)
vq_main_kernel(const float* __restrict__ x, const float* __restrict__ w,
               const float* __restrict__ bias, const float* __restrict__ cb,
               float* __restrict__ out)
{
    extern __shared__ char sm[];
    float*    WS   = (float*)(sm + SM_WS);
    uint32_t* CT   = (uint32_t*)(sm + SM_CT);
    float*    Z    = (float*)(sm + SM_Z);
    float*    CCS  = (float*)(sm + SM_CCS);
    float*    S    = (float*)(sm + SM_S);
    int*      KIDX = (int*)(sm + SM_KIDX);
    float*    CM   = (float*)(sm + SM_CM);

    const int t = threadIdx.x;
    const int lane = t & 31, wid = t >> 5;
    const int lr = lane >> 2, la = lane & 3;
    const int wm = wid * 32;

    // ---- prologue: stage weights, tf32 codebook, exact cc ----
    for (int e = t; e < DIM * CIN; e += THREADS) WS[e] = w[e];
    for (int e4 = t; e4 < KCODES * 16; e4 += THREADS) {
        const int k = e4 >> 4, d0 = (e4 & 15) << 2;
        const float4 v = *(const float4*)&cb[k * DIM + d0];
        uint32_t* p = &CT[k * ZSTRIDE + d0];
        p[0] = f2tf32(v.x); p[1] = f2tf32(v.y); p[2] = f2tf32(v.z); p[3] = f2tf32(v.w);
    }
    for (int k = t; k < KCODES; k += THREADS) {     // exact round-1 cc chain
        float s = 0.f;
#pragma unroll 8
        for (int i = 0; i < DIM; i++) { const float v = __ldg(&cb[k * DIM + i]); s = fmaf(v, v, s); }
        CCS[k] = s;
    }
    __syncthreads();
    if (t < 32) {
        float m = 0.f;
        for (int i = t; i < KCODES; i += 32) m = fmaxf(m, CCS[i]);
#pragma unroll
        for (int o = 16; o > 0; o >>= 1) m = fmaxf(m, __shfl_xor_sync(0xffffffffu, m, o));
        if (t == 0) CM[0] = sqrtf(m) * 7.8125e-3f;   // 8 * 2^-10 * sqrt(cc_max)
    }
    __syncthreads();
    const float MC = CM[0];

    for (int tile = blockIdx.x; tile < NTILES; tile += gridDim.x) {
        // ---- exact conv for this thread's pixel ----
        float z[DIM];
        conv_pixel(x, bias, WS, tile, t, z);
        float s = 0.f;                               // exact round-1 ||z||^2 chain
#pragma unroll
        for (int d = 0; d < DIM; d++) s = fmaf(z[d], z[d], s);

        __syncthreads();                             // previous tile's readers done
#pragma unroll
        for (int g = 0; g < 16; g++)
            *(float4*)&Z[t * ZSTRIDE + g * 4] =
                make_float4(z[g*4], z[g*4+1], z[g*4+2], z[g*4+3]);
        S[t] = s;
        __syncthreads();

        // ---- A fragments (tf32) for this warp's 32 rows ----
        uint32_t af[2][8][4];
#pragma unroll
        for (int m = 0; m < 2; m++) {
            const int mb = wm + m * 16;
#pragma unroll
            for (int kb = 0; kb < 8; kb++) {
                af[m][kb][0] = f2tf32(Z[(mb + lr    ) * ZSTRIDE + kb*8 + la    ]);
                af[m][kb][1] = f2tf32(Z[(mb + lr + 8) * ZSTRIDE + kb*8 + la    ]);
                af[m][kb][2] = f2tf32(Z[(mb + lr    ) * ZSTRIDE + kb*8 + la + 4]);
                af[m][kb][3] = f2tf32(Z[(mb + lr + 8) * ZSTRIDE + kb*8 + la + 4]);
            }
        }

        // ---- pass 1: tf32 estimate minima per row ----
        float emin[2][2] = {{CUDART_INF_F, CUDART_INF_F}, {CUDART_INF_F, CUDART_INF_F}};
        for (int nb = 0; nb < 64; nb++) {
            uint32_t bf[8][2];
#pragma unroll
            for (int kb = 0; kb < 8; kb++) {
                bf[kb][0] = CT[(nb*8 + lr) * ZSTRIDE + kb*8 + la    ];
                bf[kb][1] = CT[(nb*8 + lr) * ZSTRIDE + kb*8 + la + 4];
            }
            const float cc0 = CCS[nb*8 + 2*la], cc1 = CCS[nb*8 + 2*la + 1];
#pragma unroll
            for (int m = 0; m < 2; m++) {
                float c0 = 0.f, c1 = 0.f, c2 = 0.f, c3 = 0.f;
#pragma unroll
                for (int kb = 0; kb < 8; kb++)
                    mma8(c0, c1, c2, c3,
                         af[m][kb][0], af[m][kb][1], af[m][kb][2], af[m][kb][3],
                         bf[kb][0], bf[kb][1]);
                const float e0 = fmaf(-2.f, c0, cc0), e1 = fmaf(-2.f, c1, cc1);
                const float e2 = fmaf(-2.f, c2, cc0), e3 = fmaf(-2.f, c3, cc1);
                emin[m][0] = fminf(emin[m][0], fminf(e0, e1));
                emin[m][1] = fminf(emin[m][1], fminf(e2, e3));
            }
        }
        float th[2][2], srow[2][2];
#pragma unroll
        for (int m = 0; m < 2; m++)
#pragma unroll
            for (int h = 0; h < 2; h++) {
                float v = emin[m][h];
                v = fminf(v, __shfl_xor_sync(0xffffffffu, v, 1));
                v = fminf(v, __shfl_xor_sync(0xffffffffu, v, 2));
                const int r = wm + m*16 + lr + 8*h;
                srow[m][h] = S[r];
                th[m][h] = v + sqrtf(srow[m][h]) * MC + 1e-6f;
            }

        // ---- pass 2: filter + exact fp32 rescore (round-1 chain) ----
        float bdd[2][2] = {{CUDART_INF_F, CUDART_INF_F}, {CUDART_INF_F, CUDART_INF_F}};
        int   bk [2][2] = {{0, 0}, {0, 0}};
        for (int nb = 0; nb < 64; nb++) {
            uint32_t bf[8][2];
#pragma unroll
            for (int kb = 0; kb < 8; kb++) {
                bf[kb][0] = CT[(nb*8 + lr) * ZSTRIDE + kb*8 + la    ];
                bf[kb][1] = CT[(nb*8 + lr) * ZSTRIDE + kb*8 + la + 4];
            }
            const float cc0 = CCS[nb*8 + 2*la], cc1 = CCS[nb*8 + 2*la + 1];
#pragma unroll
            for (int m = 0; m < 2; m++) {
                float c0 = 0.f, c1 = 0.f, c2 = 0.f, c3 = 0.f;
#pragma unroll
                for (int kb = 0; kb < 8; kb++)
                    mma8(c0, c1, c2, c3,
                         af[m][kb][0], af[m][kb][1], af[m][kb][2], af[m][kb][3],
                         bf[kb][0], bf[kb][1]);
                float e[4];
                e[0] = fmaf(-2.f, c0, cc0); e[1] = fmaf(-2.f, c1, cc1);
                e[2] = fmaf(-2.f, c2, cc0); e[3] = fmaf(-2.f, c3, cc1);
#pragma unroll
                for (int q = 0; q < 4; q++) {
                    const int h = q >> 1;
                    if (e[q] <= th[m][h]) {
                        const int k = nb*8 + 2*la + (q & 1);
                        const int r = wm + m*16 + lr + 8*h;
                        const float* zr = &Z[r * ZSTRIDE];
                        const float* ck = &cb[k * DIM];
                        float m2 = 0.f;
#pragma unroll
                        for (int i4 = 0; i4 < 16; i4++) {
                            const float4 zv = *(const float4*)&zr[i4 * 4];
                            const float4 cv = __ldg((const float4*)&ck[i4 * 4]);
                            m2 = fmaf(cv.x, zv.x, m2); m2 = fmaf(cv.y, zv.y, m2);
                            m2 = fmaf(cv.z, zv.z, m2); m2 = fmaf(cv.w, zv.w, m2);
                        }
                        const float dd = (srow[m][h] - 2.f * m2) + CCS[k];
                        if (dd < bdd[m][h] || (dd == bdd[m][h] && k < bk[m][h])) {
                            bdd[m][h] = dd; bk[m][h] = k;
                        }
                    }
                }
            }
        }

        // ---- cross-lane (quad) argmin reduce, first-occurrence ties ----
#pragma unroll
        for (int m = 0; m < 2; m++)
#pragma unroll
            for (int h = 0; h < 2; h++) {
                float d = bdd[m][h]; int k = bk[m][h];
#pragma unroll
                for (int o = 1; o < 4; o <<= 1) {
                    const float d2 = __shfl_xor_sync(0xffffffffu, d, o);
                    const int   k2 = __shfl_xor_sync(0xffffffffu, k, o);
                    if (d2 < d || (d2 == d && k2 < k)) { d = d2; k = k2; }
                }
                if (la == 0) KIDX[wm + m*16 + lr + 8*h] = k;
            }
        __syncthreads();

        // ---- output + loss (exact round-1 order) ----
        {
            const int P = tile * TILE + t, bb = P >> 12, pp = P & 4095;
            const int k = KIDX[t];
            const float* ck = &cb[k * DIM];
            float lsum = 0.f;
#pragma unroll
            for (int i4 = 0; i4 < 16; i4++) {
                const float4 q4 = __ldg((const float4*)&ck[i4 * 4]);
                const float4 zv = *(const float4*)&Z[t * ZSTRIDE + i4 * 4];
                float df;
                df = q4.x - zv.x; out[(bb*DIM + i4*4+0)*PPIX + pp] = zv.x + df; lsum = fmaf(df, df, lsum);
                df = q4.y - zv.y; out[(bb*DIM + i4*4+1)*PPIX + pp] = zv.y + df; lsum = fmaf(df, df, lsum);
                df = q4.z - zv.z; out[(bb*DIM + i4*4+2)*PPIX + pp] = zv.z + df; lsum = fmaf(df, df, lsum);
                df = q4.w - zv.w; out[(bb*DIM + i4*4+3)*PPIX + pp] = zv.w + df; lsum = fmaf(df, df, lsum);
            }
            double dl = (double)lsum;
#pragma unroll
            for (int o = 16; o > 0; o >>= 1) dl += __shfl_down_sync(0xffffffffu, dl, o);
            if (lane == 0) atomicAdd(&g_loss_sum, dl);
        }
    }
}

__global__ void vq_fin_kernel(float* __restrict__ out, int out_size) {
    if (out_size > NOUTE) {
        const float m = (float)(g_loss_sum / (double)NOUTE);
        out[NOUTE] = 0.25f * m + m;
    }
}

extern "C" void kernel_launch(void* const* d_in, const int* in_sizes, int n_in,
                              void* d_out, int out_size)
{
    const float* x    = (const float*)d_in[0];
    const float* w    = (const float*)d_in[1];
    const float* bias = (const float*)d_in[2];
    const float* cb   = (const float*)d_in[3];
    float* out = (float*)d_out;

    int sms = 148;
    cudaDeviceGetAttribute(&sms, cudaDevAttrMultiProcessorCount, 0);

    cudaFuncSetAttribute(vq_main_kernel, cudaFuncAttributeMaxDynamicSharedMemorySize, SM_TOTAL);

    vq_init_kernel<<<1, 1>>>();
    vq_main_kernel<<<sms, THREADS, SM_TOTAL>>>(x, w, bias, cb, out);
    vq_fin_kernel<<<1, 1>>>(out, out_size);
}